// round 13
// baseline (speedup 1.0000x reference)
#include <cuda_runtime.h>
#include <cuda_bf16.h>
#include <math.h>
#include <cstdint>

#define Bn 8
#define Cn 64
#define HW 65536
#define Sn 2048
#define OUTC 16

#define F_SCALE     20.6096954f                   /* log2(e)/0.07 */
#define F_LN2       0.69314718056f

typedef unsigned long long ull;
__device__ __forceinline__ ull pack2(float lo, float hi) {
    ull r;
    asm("mov.b64 %0, {%1, %2};" : "=l"(r) : "r"(__float_as_uint(lo)), "r"(__float_as_uint(hi)));
    return r;
}
__device__ __forceinline__ void unpack2(ull v, float& lo, float& hi) {
    unsigned a, b;
    asm("mov.b64 {%0, %1}, %2;" : "=r"(a), "=r"(b) : "l"(v));
    lo = __uint_as_float(a); hi = __uint_as_float(b);
}
#define FMA2(d, a, b) asm("fma.rn.f32x2 %0, %1, %2, %3;" : "=l"(d) : "l"(a), "l"(b), "l"(d))
#define ADD2(d, a)    asm("add.rn.f32x2 %0, %1, %2;"     : "=l"(d) : "l"(a), "l"(d))
__device__ __forceinline__ float ex2f(float x) {
    float y; asm("ex2.approx.f32 %0, %1;" : "=f"(y) : "f"(x)); return y;
}
__device__ __forceinline__ float lg2f(float x) {
    float y; asm("lg2.approx.f32 %0, %1;" : "=f"(y) : "f"(x)); return y;
}
#define PACKBF(d, lo, hi) \
    asm("cvt.rn.bf16x2.f32 %0, %1, %2;" : "=r"(d) : "f"(hi), "f"(lo))

// m16n8k16 bf16 MMA, C = 0 (K=16 == OUTC: one MMA = finished dot tile)
__device__ __forceinline__ void mma16816(float& d0, float& d1, float& d2, float& d3,
                                         uint32_t a0, uint32_t a1, uint32_t a2, uint32_t a3,
                                         uint32_t b0, uint32_t b1) {
    asm("mma.sync.aligned.m16n8k16.row.col.f32.bf16.bf16.f32 "
        "{%0,%1,%2,%3}, {%4,%5,%6,%7}, {%8,%9}, {%10,%11,%12,%13};"
        : "=f"(d0), "=f"(d1), "=f"(d2), "=f"(d3)
        : "r"(a0), "r"(a1), "r"(a2), "r"(a3), "r"(b0), "r"(b1),
          "f"(0.0f), "f"(0.0f), "f"(0.0f), "f"(0.0f));
}

// Scratch
__device__ float g_diff[2 * Bn * Cn * Sn];      // 8 MB
__device__ float g_fq[Bn * Sn * OUTC];
__device__ float g_fk[Bn * Sn * OUTC];
__device__ __align__(16) __nv_bfloat16 g_fqh[Bn * Sn * OUTC];
__device__ __align__(16) __nv_bfloat16 g_fkh[Bn * Sn * OUTC];

// ---------------------------------------------------------------------------
// Kernel A: gather + diff (+ zero out).
//   Sample permutation: s' = center*8 + off (valid: loss is a row-mean over a
//   full Gram; both maps use the same permutation, diagonal pairing intact).
//   Thread j: burst-load the 3x3 stencil (9 loads, sector reuse in L1),
//   compute 8 diffs, 2x STG.128.  Neighbor offsets are problem constants.
// ---------------------------------------------------------------------------
__global__ void gather_diff_kernel(const float* __restrict__ fq,
                                   const float* __restrict__ fk,
                                   const int*   __restrict__ c_ids,
                                   float* __restrict__ out) {
    if (blockIdx.x == 0 && threadIdx.x == 0) out[0] = 0.0f;

    int gid = blockIdx.x;
    int map = gid >> 9;
    int bc  = gid & 511;
    int b   = bc >> 6;
    int c   = bc & 63;

    const float* feat = (map ? fk : fq) + ((size_t)b * Cn + c) * HW;
    float* dst = g_diff + ((size_t)(map * Bn + b) * Cn + c) * Sn;

    int j = threadIdx.x;            // center index 0..255
    int ic = __ldg(&c_ids[j]);

    // 3x3 stencil, all loads issued back-to-back (W = 256)
    const float* p = feat + ic;
    float fc  = __ldg(p);
    float n0  = __ldg(p - 257);     // -(W+1)
    float n1  = __ldg(p - 256);     // -W
    float n2  = __ldg(p - 255);     // -(W-1)
    float n3  = __ldg(p - 1);       // -1
    float n4  = __ldg(p + 1);       // +1
    float n5  = __ldg(p + 255);     // W-1
    float n6  = __ldg(p + 256);     // W
    float n7  = __ldg(p + 257);     // W+1

    float4 d0 = make_float4(fc - n0, fc - n1, fc - n2, fc - n3);
    float4 d1 = make_float4(fc - n4, fc - n5, fc - n6, fc - n7);
    float4* dv = reinterpret_cast<float4*>(dst + (size_t)j * 8);
    dv[0] = d0;
    dv[1] = d1;
}

// ---------------------------------------------------------------------------
// Kernel B: MLP + L2-normalize; emits fp32 AND bf16 embeddings.
// ---------------------------------------------------------------------------
#define XPAD 68
__global__ __launch_bounds__(256) void mlp_kernel(const float* __restrict__ W0,
                                                  const float* __restrict__ b0,
                                                  const float* __restrict__ W1,
                                                  const float* __restrict__ b1) {
    extern __shared__ float smem[];
    float* sx  = smem;                       // 256*68
    float* sW0 = sx + 256 * XPAD;            // 64*64 (transposed)
    float* sW1 = sW0 + 64 * 64;              // 64*16
    float* sb0 = sW1 + 64 * 16;              // 64
    float* sb1 = sb0 + 64;                   // 16

    int mb = blockIdx.x >> 3;
    int s0 = (blockIdx.x & 7) * 256;
    int tid = threadIdx.x;

    const float* src = g_diff + (size_t)mb * Cn * Sn;

    for (int i = tid; i < 4096; i += 256) {
        int c = i >> 6, t = i & 63;
        sW0[t * 64 + c] = __ldg(&W0[i]);
    }
    for (int i = tid; i < 1024; i += 256) sW1[i] = __ldg(&W1[i]);
    if (tid < 64) sb0[tid] = __ldg(&b0[tid]);
    if (tid < 16) sb1[tid] = __ldg(&b1[tid]);

    for (int i = tid; i < 64 * 256; i += 256) {
        int c = i >> 8, s = i & 255;
        sx[s * XPAD + c] = src[(size_t)c * Sn + s0 + s];
    }
    __syncthreads();

    ull x2[32];
#pragma unroll
    for (int i = 0; i < 16; i++) {
        float4 v = *reinterpret_cast<float4*>(&sx[tid * XPAD + i * 4]);
        x2[2 * i + 0] = pack2(v.x, v.y);
        x2[2 * i + 1] = pack2(v.z, v.w);
    }

    ull o2[8];
#pragma unroll
    for (int i = 0; i < 8; i++) o2[i] = pack2(sb1[2 * i], sb1[2 * i + 1]);

#pragma unroll 4
    for (int t = 0; t < 64; t++) {
        const ull* w2 = reinterpret_cast<const ull*>(&sW0[t * 64]);
        ull a0 = 0, a1 = 0, a2 = 0, a3 = 0;
#pragma unroll
        for (int i = 0; i < 8; i++) {
            FMA2(a0, x2[i +  0], w2[i +  0]);
            FMA2(a1, x2[i +  8], w2[i +  8]);
            FMA2(a2, x2[i + 16], w2[i + 16]);
            FMA2(a3, x2[i + 24], w2[i + 24]);
        }
        ADD2(a0, a1); ADD2(a2, a3); ADD2(a0, a2);
        float lo, hi; unpack2(a0, lo, hi);
        float h = fmaxf(lo + hi + sb0[t], 0.0f);
        ull h2 = pack2(h, h);
        const ull* w1 = reinterpret_cast<const ull*>(&sW1[t * 16]);
#pragma unroll
        for (int i = 0; i < 8; i++) FMA2(o2[i], h2, w1[i]);
    }

    float o[16];
#pragma unroll
    for (int i = 0; i < 8; i++) unpack2(o2[i], o[2 * i], o[2 * i + 1]);

    float sq = 0.f;
#pragma unroll
    for (int i = 0; i < 16; i++) sq = fmaf(o[i], o[i], sq);
    float inv = 1.0f / (sqrtf(sq) + 1e-7f);
#pragma unroll
    for (int i = 0; i < 16; i++) o[i] *= inv;

    size_t row = (mb < Bn) ? ((size_t)mb * Sn + s0 + tid)
                           : ((size_t)(mb - Bn) * Sn + s0 + tid);
    float* dst = (mb < Bn ? g_fq : g_fk) + row * OUTC;
#pragma unroll
    for (int oo = 0; oo < 4; oo++)
        *reinterpret_cast<float4*>(&dst[oo * 4]) =
            make_float4(o[oo * 4 + 0], o[oo * 4 + 1], o[oo * 4 + 2], o[oo * 4 + 3]);

    uint32_t hb[8];
#pragma unroll
    for (int i = 0; i < 8; i++) PACKBF(hb[i], o[2 * i], o[2 * i + 1]);
    uint32_t* dsth = reinterpret_cast<uint32_t*>(
        (mb < Bn ? g_fqh : g_fkh) + row * OUTC);
#pragma unroll
    for (int i = 0; i < 2; i++)
        reinterpret_cast<uint4*>(dsth)[i] =
            make_uint4(hb[4 * i + 0], hb[4 * i + 1], hb[4 * i + 2], hb[4 * i + 3]);
}

// ---------------------------------------------------------------------------
// Kernel C: HMMA Gram + fused softmax-sum + loss (unchanged from R12 win).
// ---------------------------------------------------------------------------
__global__ __launch_bounds__(256) void gram_kernel(float* __restrict__ out) {
    extern __shared__ uint32_t sk[];      // B0[2048*4] | B1[2048*4]  (64 KB)
    __shared__ float s_wred[8];

    int tid  = threadIdx.x;
    int w    = tid >> 5;
    int lane = tid & 31;
    int g    = lane >> 2;                 // groupID 0..7
    int t    = lane & 3;                  // threadID-in-group
    int b    = blockIdx.x >> 4;
    int rb   = blockIdx.x & 15;

    uint32_t* B0 = sk;
    uint32_t* B1 = sk + Sn * 4;

    const uint32_t* ksrc = reinterpret_cast<const uint32_t*>(g_fkh) +
                           (size_t)b * Sn * 8;
    for (int idx = tid; idx < Sn * 8; idx += 256) {
        int n = idx >> 3, j = idx & 7;
        uint32_t v = __ldg(&ksrc[idx]);
        if (j < 4) B0[n * 4 + j] = v;
        else       B1[n * 4 + (j - 4)] = v;
    }

    int r0 = rb * 128 + w * 16 + g;
    const uint32_t* qu = reinterpret_cast<const uint32_t*>(g_fqh) +
                         (size_t)b * Sn * 8;
    uint32_t a0 = __ldg(&qu[(size_t)r0 * 8 + t]);
    uint32_t a1 = __ldg(&qu[(size_t)(r0 + 8) * 8 + t]);
    uint32_t a2 = __ldg(&qu[(size_t)r0 * 8 + t + 4]);
    uint32_t a3 = __ldg(&qu[(size_t)(r0 + 8) * 8 + t + 4]);

    __syncthreads();

    float s0 = 0.f, s1 = 0.f;

    for (int j = 0; j < Sn / 8; j += 2) {
        int nA = (j + 0) * 8 + g;
        int nB = (j + 1) * 8 + g;
        uint32_t bA0 = B0[nA * 4 + t], bA1 = B1[nA * 4 + t];
        uint32_t bB0 = B0[nB * 4 + t], bB1 = B1[nB * 4 + t];

        float dA0, dA1, dA2, dA3, dB0, dB1, dB2, dB3;
        mma16816(dA0, dA1, dA2, dA3, a0, a1, a2, a3, bA0, bA1);
        mma16816(dB0, dB1, dB2, dB3, a0, a1, a2, a3, bB0, bB1);

        s0 += ex2f(fmaf(dA0, F_SCALE, -F_SCALE));
        s0 += ex2f(fmaf(dA1, F_SCALE, -F_SCALE));
        s1 += ex2f(fmaf(dA2, F_SCALE, -F_SCALE));
        s1 += ex2f(fmaf(dA3, F_SCALE, -F_SCALE));
        s0 += ex2f(fmaf(dB0, F_SCALE, -F_SCALE));
        s0 += ex2f(fmaf(dB1, F_SCALE, -F_SCALE));
        s1 += ex2f(fmaf(dB2, F_SCALE, -F_SCALE));
        s1 += ex2f(fmaf(dB3, F_SCALE, -F_SCALE));
    }

    s0 += __shfl_xor_sync(0xFFFFFFFFu, s0, 1);
    s0 += __shfl_xor_sync(0xFFFFFFFFu, s0, 2);
    s1 += __shfl_xor_sync(0xFFFFFFFFu, s1, 1);
    s1 += __shfl_xor_sync(0xFFFFFFFFu, s1, 2);

    float loss = 0.f;
    if (t == 0) {
#pragma unroll
        for (int rr = 0; rr < 2; rr++) {
            int r = (rr == 0) ? r0 : r0 + 8;
            float sum = (rr == 0) ? s0 : s1;
            size_t grow = (size_t)b * Sn + r;
            const float4* qr = reinterpret_cast<const float4*>(g_fq + grow * OUTC);
            const float4* kr = reinterpret_cast<const float4*>(g_fk + grow * OUTC);
            float d = 0.f;
#pragma unroll
            for (int jj = 0; jj < 4; jj++) {
                float4 qv = __ldg(&qr[jj]);
                float4 kv = __ldg(&kr[jj]);
                d = fmaf(qv.x, kv.x, d); d = fmaf(qv.y, kv.y, d);
                d = fmaf(qv.z, kv.z, d); d = fmaf(qv.w, kv.w, d);
            }
            loss += F_LN2 * (lg2f(sum) - F_SCALE * (d - 1.0f));
        }
    }

#pragma unroll
    for (int o = 16; o > 0; o >>= 1)
        loss += __shfl_xor_sync(0xFFFFFFFFu, loss, o);
    if (lane == 0) s_wred[w] = loss;
    __syncthreads();
    if (tid == 0) {
        float acc = 0.f;
#pragma unroll
        for (int i = 0; i < 8; i++) acc += s_wred[i];
        atomicAdd(out, acc * (1.0f / (float)(Bn * Sn)));
    }
}

// ---------------------------------------------------------------------------
extern "C" void kernel_launch(void* const* d_in, const int* in_sizes, int n_in,
                              void* d_out, int out_size) {
    const float* f_q  = (const float*)d_in[0];
    const float* f_k  = (const float*)d_in[1];
    const float* W0   = (const float*)d_in[2];
    const float* b0   = (const float*)d_in[3];
    const float* W1   = (const float*)d_in[4];
    const float* b1   = (const float*)d_in[5];
    const int*   c_id = (const int*)d_in[6];
    float* out = (float*)d_out;

    int mlp_smem = (256 * XPAD + 64 * 64 + 64 * 16 + 64 + 16) * (int)sizeof(float);
    cudaFuncSetAttribute(mlp_kernel,
                         cudaFuncAttributeMaxDynamicSharedMemorySize, mlp_smem);
    int gram_smem = Sn * 8 * (int)sizeof(uint32_t);   // 64 KB
    cudaFuncSetAttribute(gram_kernel,
                         cudaFuncAttributeMaxDynamicSharedMemorySize, gram_smem);

    gather_diff_kernel<<<2 * Bn * Cn, 256>>>(f_q, f_k, c_id, out);
    mlp_kernel<<<16 * 8, 256, mlp_smem>>>(W0, b0, W1, b1);
    gram_kernel<<<Bn * 16, 256, gram_smem>>>(out);
}

// round 14
// speedup vs baseline: 1.1427x; 1.1427x over previous
#include <cuda_runtime.h>
#include <cuda_bf16.h>
#include <math.h>
#include <cstdint>

#define Bn 8
#define Cn 64
#define HW 65536
#define Sn 2048
#define OUTC 16

#define F_SCALE     20.6096954f                   /* log2(e)/0.07 */
#define F_LN2       0.69314718056f

typedef unsigned long long ull;
__device__ __forceinline__ ull pack2(float lo, float hi) {
    ull r;
    asm("mov.b64 %0, {%1, %2};" : "=l"(r) : "r"(__float_as_uint(lo)), "r"(__float_as_uint(hi)));
    return r;
}
__device__ __forceinline__ void unpack2(ull v, float& lo, float& hi) {
    unsigned a, b;
    asm("mov.b64 {%0, %1}, %2;" : "=r"(a), "=r"(b) : "l"(v));
    lo = __uint_as_float(a); hi = __uint_as_float(b);
}
#define FMA2(d, a, b) asm("fma.rn.f32x2 %0, %1, %2, %3;" : "=l"(d) : "l"(a), "l"(b), "l"(d))
#define ADD2(d, a)    asm("add.rn.f32x2 %0, %1, %2;"     : "=l"(d) : "l"(a), "l"(d))
__device__ __forceinline__ float ex2f(float x) {
    float y; asm("ex2.approx.f32 %0, %1;" : "=f"(y) : "f"(x)); return y;
}
__device__ __forceinline__ float lg2f(float x) {
    float y; asm("lg2.approx.f32 %0, %1;" : "=f"(y) : "f"(x)); return y;
}
#define PACKBF(d, lo, hi) \
    asm("cvt.rn.bf16x2.f32 %0, %1, %2;" : "=r"(d) : "f"(hi), "f"(lo))

// m16n8k16 bf16 MMA, C = 0
__device__ __forceinline__ void mma16816(float& d0, float& d1, float& d2, float& d3,
                                         uint32_t a0, uint32_t a1, uint32_t a2, uint32_t a3,
                                         uint32_t b0, uint32_t b1) {
    asm("mma.sync.aligned.m16n8k16.row.col.f32.bf16.bf16.f32 "
        "{%0,%1,%2,%3}, {%4,%5,%6,%7}, {%8,%9}, {%10,%11,%12,%13};"
        : "=f"(d0), "=f"(d1), "=f"(d2), "=f"(d3)
        : "r"(a0), "r"(a1), "r"(a2), "r"(a3), "r"(b0), "r"(b1),
          "f"(0.0f), "f"(0.0f), "f"(0.0f), "f"(0.0f));
}

// Scratch (g_diff eliminated)
__device__ float g_fq[Bn * Sn * OUTC];
__device__ float g_fk[Bn * Sn * OUTC];
__device__ __align__(16) __nv_bfloat16 g_fqh[Bn * Sn * OUTC];
__device__ __align__(16) __nv_bfloat16 g_fkh[Bn * Sn * OUTC];

// ---------------------------------------------------------------------------
// Kernel AB (fused): gather stencil diffs straight into the MLP's smem tile,
// then MLP + L2-normalize.  grid = 16 mb x 8 chunks = 128 blocks, 256 thr.
//   Gather: pair (ce, c); lane = channel c -> STS sx[(ce*8+off)*XPAD + c]
//   conflict-free; 9-load stencil bursts keep DRAM saturated while other
//   blocks' MLP phases run.  Sample permutation s = center*8 + off (as R13).
// ---------------------------------------------------------------------------
#define XPAD 68
__global__ __launch_bounds__(256) void gmlp_kernel(const float* __restrict__ fq,
                                                   const float* __restrict__ fk,
                                                   const int*   __restrict__ c_ids,
                                                   const float* __restrict__ W0,
                                                   const float* __restrict__ b0,
                                                   const float* __restrict__ W1,
                                                   const float* __restrict__ b1,
                                                   float* __restrict__ out) {
    extern __shared__ float smem[];
    float* sx  = smem;                       // 256*68
    float* sW0 = sx + 256 * XPAD;            // 64*64 (transposed)
    float* sW1 = sW0 + 64 * 64;              // 64*16
    float* sb0 = sW1 + 64 * 16;              // 64
    float* sb1 = sb0 + 64;                   // 16

    if (blockIdx.x == 0 && threadIdx.x == 0) out[0] = 0.0f;

    int mb    = blockIdx.x >> 3;             // 0..15 (map*8 + b)
    int chunk = blockIdx.x & 7;              // 32 centers -> 256 rows
    int tid   = threadIdx.x;
    int b     = (mb < Bn) ? mb : mb - Bn;

    // weights -> smem (overlaps with gather loads below)
    for (int i = tid; i < 4096; i += 256) {
        int c = i >> 6, t = i & 63;
        sW0[t * 64 + c] = __ldg(&W0[i]);
    }
    for (int i = tid; i < 1024; i += 256) sW1[i] = __ldg(&W1[i]);
    if (tid < 64) sb0[tid] = __ldg(&b0[tid]);
    if (tid < 16) sb1[tid] = __ldg(&b1[tid]);

    // gather: this thread = channel c, centers ce0, ce0+4, ..., ce0+28
    {
        int c   = tid & 63;
        int ce0 = tid >> 6;
        const float* featc = ((mb < Bn) ? fq : fk) + ((size_t)b * Cn + c) * HW;
#pragma unroll
        for (int k = 0; k < 8; k++) {
            int ce = ce0 + 4 * k;
            int ic = __ldg(&c_ids[chunk * 32 + ce]);
            const float* p = featc + ic;
            float fc  = __ldg(p);
            float n0  = __ldg(p - 257);
            float n1  = __ldg(p - 256);
            float n2  = __ldg(p - 255);
            float n3  = __ldg(p - 1);
            float n4  = __ldg(p + 1);
            float n5  = __ldg(p + 255);
            float n6  = __ldg(p + 256);
            float n7  = __ldg(p + 257);
            float* sxr = sx + (size_t)(ce * 8) * XPAD + c;
            sxr[0 * XPAD] = fc - n0;
            sxr[1 * XPAD] = fc - n1;
            sxr[2 * XPAD] = fc - n2;
            sxr[3 * XPAD] = fc - n3;
            sxr[4 * XPAD] = fc - n4;
            sxr[5 * XPAD] = fc - n5;
            sxr[6 * XPAD] = fc - n6;
            sxr[7 * XPAD] = fc - n7;
        }
    }
    __syncthreads();

    // ---- MLP body (thread = row) ----
    ull x2[32];
#pragma unroll
    for (int i = 0; i < 16; i++) {
        float4 v = *reinterpret_cast<float4*>(&sx[tid * XPAD + i * 4]);
        x2[2 * i + 0] = pack2(v.x, v.y);
        x2[2 * i + 1] = pack2(v.z, v.w);
    }

    ull o2[8];
#pragma unroll
    for (int i = 0; i < 8; i++) o2[i] = pack2(sb1[2 * i], sb1[2 * i + 1]);

#pragma unroll 4
    for (int t = 0; t < 64; t++) {
        const ull* w2 = reinterpret_cast<const ull*>(&sW0[t * 64]);
        ull a0 = 0, a1 = 0, a2 = 0, a3 = 0;
#pragma unroll
        for (int i = 0; i < 8; i++) {
            FMA2(a0, x2[i +  0], w2[i +  0]);
            FMA2(a1, x2[i +  8], w2[i +  8]);
            FMA2(a2, x2[i + 16], w2[i + 16]);
            FMA2(a3, x2[i + 24], w2[i + 24]);
        }
        ADD2(a0, a1); ADD2(a2, a3); ADD2(a0, a2);
        float lo, hi; unpack2(a0, lo, hi);
        float h = fmaxf(lo + hi + sb0[t], 0.0f);
        ull h2 = pack2(h, h);
        const ull* w1 = reinterpret_cast<const ull*>(&sW1[t * 16]);
#pragma unroll
        for (int i = 0; i < 8; i++) FMA2(o2[i], h2, w1[i]);
    }

    float o[16];
#pragma unroll
    for (int i = 0; i < 8; i++) unpack2(o2[i], o[2 * i], o[2 * i + 1]);

    float sq = 0.f;
#pragma unroll
    for (int i = 0; i < 16; i++) sq = fmaf(o[i], o[i], sq);
    float inv = 1.0f / (sqrtf(sq) + 1e-7f);
#pragma unroll
    for (int i = 0; i < 16; i++) o[i] *= inv;

    size_t row = (size_t)b * Sn + chunk * 256 + tid;
    float* dst = (mb < Bn ? g_fq : g_fk) + row * OUTC;
#pragma unroll
    for (int oo = 0; oo < 4; oo++)
        *reinterpret_cast<float4*>(&dst[oo * 4]) =
            make_float4(o[oo * 4 + 0], o[oo * 4 + 1], o[oo * 4 + 2], o[oo * 4 + 3]);

    uint32_t hb[8];
#pragma unroll
    for (int i = 0; i < 8; i++) PACKBF(hb[i], o[2 * i], o[2 * i + 1]);
    uint32_t* dsth = reinterpret_cast<uint32_t*>(
        (mb < Bn ? g_fqh : g_fkh) + row * OUTC);
#pragma unroll
    for (int i = 0; i < 2; i++)
        reinterpret_cast<uint4*>(dsth)[i] =
            make_uint4(hb[4 * i + 0], hb[4 * i + 1], hb[4 * i + 2], hb[4 * i + 3]);
}

// ---------------------------------------------------------------------------
// Kernel C: HMMA Gram + fused softmax-sum + loss (unchanged from R12 win).
// ---------------------------------------------------------------------------
__global__ __launch_bounds__(256) void gram_kernel(float* __restrict__ out) {
    extern __shared__ uint32_t sk[];      // B0[2048*4] | B1[2048*4]  (64 KB)
    __shared__ float s_wred[8];

    int tid  = threadIdx.x;
    int w    = tid >> 5;
    int lane = tid & 31;
    int g    = lane >> 2;
    int t    = lane & 3;
    int b    = blockIdx.x >> 4;
    int rb   = blockIdx.x & 15;

    uint32_t* B0 = sk;
    uint32_t* B1 = sk + Sn * 4;

    const uint32_t* ksrc = reinterpret_cast<const uint32_t*>(g_fkh) +
                           (size_t)b * Sn * 8;
    for (int idx = tid; idx < Sn * 8; idx += 256) {
        int n = idx >> 3, j = idx & 7;
        uint32_t v = __ldg(&ksrc[idx]);
        if (j < 4) B0[n * 4 + j] = v;
        else       B1[n * 4 + (j - 4)] = v;
    }

    int r0 = rb * 128 + w * 16 + g;
    const uint32_t* qu = reinterpret_cast<const uint32_t*>(g_fqh) +
                         (size_t)b * Sn * 8;
    uint32_t a0 = __ldg(&qu[(size_t)r0 * 8 + t]);
    uint32_t a1 = __ldg(&qu[(size_t)(r0 + 8) * 8 + t]);
    uint32_t a2 = __ldg(&qu[(size_t)r0 * 8 + t + 4]);
    uint32_t a3 = __ldg(&qu[(size_t)(r0 + 8) * 8 + t + 4]);

    __syncthreads();

    float s0 = 0.f, s1 = 0.f;

    for (int j = 0; j < Sn / 8; j += 2) {
        int nA = (j + 0) * 8 + g;
        int nB = (j + 1) * 8 + g;
        uint32_t bA0 = B0[nA * 4 + t], bA1 = B1[nA * 4 + t];
        uint32_t bB0 = B0[nB * 4 + t], bB1 = B1[nB * 4 + t];

        float dA0, dA1, dA2, dA3, dB0, dB1, dB2, dB3;
        mma16816(dA0, dA1, dA2, dA3, a0, a1, a2, a3, bA0, bA1);
        mma16816(dB0, dB1, dB2, dB3, a0, a1, a2, a3, bB0, bB1);

        s0 += ex2f(fmaf(dA0, F_SCALE, -F_SCALE));
        s0 += ex2f(fmaf(dA1, F_SCALE, -F_SCALE));
        s1 += ex2f(fmaf(dA2, F_SCALE, -F_SCALE));
        s1 += ex2f(fmaf(dA3, F_SCALE, -F_SCALE));
        s0 += ex2f(fmaf(dB0, F_SCALE, -F_SCALE));
        s0 += ex2f(fmaf(dB1, F_SCALE, -F_SCALE));
        s1 += ex2f(fmaf(dB2, F_SCALE, -F_SCALE));
        s1 += ex2f(fmaf(dB3, F_SCALE, -F_SCALE));
    }

    s0 += __shfl_xor_sync(0xFFFFFFFFu, s0, 1);
    s0 += __shfl_xor_sync(0xFFFFFFFFu, s0, 2);
    s1 += __shfl_xor_sync(0xFFFFFFFFu, s1, 1);
    s1 += __shfl_xor_sync(0xFFFFFFFFu, s1, 2);

    float loss = 0.f;
    if (t == 0) {
#pragma unroll
        for (int rr = 0; rr < 2; rr++) {
            int r = (rr == 0) ? r0 : r0 + 8;
            float sum = (rr == 0) ? s0 : s1;
            size_t grow = (size_t)b * Sn + r;
            const float4* qr = reinterpret_cast<const float4*>(g_fq + grow * OUTC);
            const float4* kr = reinterpret_cast<const float4*>(g_fk + grow * OUTC);
            float d = 0.f;
#pragma unroll
            for (int jj = 0; jj < 4; jj++) {
                float4 qv = __ldg(&qr[jj]);
                float4 kv = __ldg(&kr[jj]);
                d = fmaf(qv.x, kv.x, d); d = fmaf(qv.y, kv.y, d);
                d = fmaf(qv.z, kv.z, d); d = fmaf(qv.w, kv.w, d);
            }
            loss += F_LN2 * (lg2f(sum) - F_SCALE * (d - 1.0f));
        }
    }

#pragma unroll
    for (int o = 16; o > 0; o >>= 1)
        loss += __shfl_xor_sync(0xFFFFFFFFu, loss, o);
    if (lane == 0) s_wred[w] = loss;
    __syncthreads();
    if (tid == 0) {
        float acc = 0.f;
#pragma unroll
        for (int i = 0; i < 8; i++) acc += s_wred[i];
        atomicAdd(out, acc * (1.0f / (float)(Bn * Sn)));
    }
}

// ---------------------------------------------------------------------------
extern "C" void kernel_launch(void* const* d_in, const int* in_sizes, int n_in,
                              void* d_out, int out_size) {
    const float* f_q  = (const float*)d_in[0];
    const float* f_k  = (const float*)d_in[1];
    const float* W0   = (const float*)d_in[2];
    const float* b0   = (const float*)d_in[3];
    const float* W1   = (const float*)d_in[4];
    const float* b1   = (const float*)d_in[5];
    const int*   c_id = (const int*)d_in[6];
    float* out = (float*)d_out;

    int gmlp_smem = (256 * XPAD + 64 * 64 + 64 * 16 + 64 + 16) * (int)sizeof(float);
    cudaFuncSetAttribute(gmlp_kernel,
                         cudaFuncAttributeMaxDynamicSharedMemorySize, gmlp_smem);
    int gram_smem = Sn * 8 * (int)sizeof(uint32_t);   // 64 KB
    cudaFuncSetAttribute(gram_kernel,
                         cudaFuncAttributeMaxDynamicSharedMemorySize, gram_smem);

    gmlp_kernel<<<16 * 8, 256, gmlp_smem>>>(f_q, f_k, c_id, W0, b0, W1, b1, out);
    gram_kernel<<<Bn * 16, 256, gram_smem>>>(out);
}

// round 15
// speedup vs baseline: 1.1699x; 1.0239x over previous
#include <cuda_runtime.h>
#include <cuda_bf16.h>
#include <math.h>
#include <cstdint>

#define Bn 8
#define Cn 64
#define HW 65536
#define Sn 2048
#define OUTC 16

#define F_SCALE     20.6096954f                   /* log2(e)/0.07 */
#define F_LN2       0.69314718056f

typedef unsigned long long ull;
__device__ __forceinline__ ull pack2(float lo, float hi) {
    ull r;
    asm("mov.b64 %0, {%1, %2};" : "=l"(r) : "r"(__float_as_uint(lo)), "r"(__float_as_uint(hi)));
    return r;
}
__device__ __forceinline__ void unpack2(ull v, float& lo, float& hi) {
    unsigned a, b;
    asm("mov.b64 {%0, %1}, %2;" : "=r"(a), "=r"(b) : "l"(v));
    lo = __uint_as_float(a); hi = __uint_as_float(b);
}
#define FMA2(d, a, b) asm("fma.rn.f32x2 %0, %1, %2, %3;" : "=l"(d) : "l"(a), "l"(b), "l"(d))
#define ADD2(d, a)    asm("add.rn.f32x2 %0, %1, %2;"     : "=l"(d) : "l"(a), "l"(d))
__device__ __forceinline__ float ex2f(float x) {
    float y; asm("ex2.approx.f32 %0, %1;" : "=f"(y) : "f"(x)); return y;
}
__device__ __forceinline__ float lg2f(float x) {
    float y; asm("lg2.approx.f32 %0, %1;" : "=f"(y) : "f"(x)); return y;
}
#define PACKBF(d, lo, hi) \
    asm("cvt.rn.bf16x2.f32 %0, %1, %2;" : "=r"(d) : "f"(hi), "f"(lo))

// m16n8k16 bf16 MMA, C = 0
__device__ __forceinline__ void mma16816(float& d0, float& d1, float& d2, float& d3,
                                         uint32_t a0, uint32_t a1, uint32_t a2, uint32_t a3,
                                         uint32_t b0, uint32_t b1) {
    asm("mma.sync.aligned.m16n8k16.row.col.f32.bf16.bf16.f32 "
        "{%0,%1,%2,%3}, {%4,%5,%6,%7}, {%8,%9}, {%10,%11,%12,%13};"
        : "=f"(d0), "=f"(d1), "=f"(d2), "=f"(d3)
        : "r"(a0), "r"(a1), "r"(a2), "r"(a3), "r"(b0), "r"(b1),
          "f"(0.0f), "f"(0.0f), "f"(0.0f), "f"(0.0f));
}

// Scratch
__device__ float g_fq[Bn * Sn * OUTC];
__device__ float g_fk[Bn * Sn * OUTC];
__device__ __align__(16) __nv_bfloat16 g_fqh[Bn * Sn * OUTC];
__device__ __align__(16) __nv_bfloat16 g_fkh[Bn * Sn * OUTC];

// ---------------------------------------------------------------------------
// Kernel AB (fused): gather stencil diffs into smem, MLP + L2-norm.
// (unchanged from R14 win)
// ---------------------------------------------------------------------------
#define XPAD 68
__global__ __launch_bounds__(256) void gmlp_kernel(const float* __restrict__ fq,
                                                   const float* __restrict__ fk,
                                                   const int*   __restrict__ c_ids,
                                                   const float* __restrict__ W0,
                                                   const float* __restrict__ b0,
                                                   const float* __restrict__ W1,
                                                   const float* __restrict__ b1,
                                                   float* __restrict__ out) {
    extern __shared__ float smem[];
    float* sx  = smem;                       // 256*68
    float* sW0 = sx + 256 * XPAD;            // 64*64 (transposed)
    float* sW1 = sW0 + 64 * 64;              // 64*16
    float* sb0 = sW1 + 64 * 16;              // 64
    float* sb1 = sb0 + 64;                   // 16

    if (blockIdx.x == 0 && threadIdx.x == 0) out[0] = 0.0f;

    int mb    = blockIdx.x >> 3;
    int chunk = blockIdx.x & 7;
    int tid   = threadIdx.x;
    int b     = (mb < Bn) ? mb : mb - Bn;

    for (int i = tid; i < 4096; i += 256) {
        int c = i >> 6, t = i & 63;
        sW0[t * 64 + c] = __ldg(&W0[i]);
    }
    for (int i = tid; i < 1024; i += 256) sW1[i] = __ldg(&W1[i]);
    if (tid < 64) sb0[tid] = __ldg(&b0[tid]);
    if (tid < 16) sb1[tid] = __ldg(&b1[tid]);

    {
        int c   = tid & 63;
        int ce0 = tid >> 6;
        const float* featc = ((mb < Bn) ? fq : fk) + ((size_t)b * Cn + c) * HW;
#pragma unroll
        for (int k = 0; k < 8; k++) {
            int ce = ce0 + 4 * k;
            int ic = __ldg(&c_ids[chunk * 32 + ce]);
            const float* p = featc + ic;
            float fc  = __ldg(p);
            float n0  = __ldg(p - 257);
            float n1  = __ldg(p - 256);
            float n2  = __ldg(p - 255);
            float n3  = __ldg(p - 1);
            float n4  = __ldg(p + 1);
            float n5  = __ldg(p + 255);
            float n6  = __ldg(p + 256);
            float n7  = __ldg(p + 257);
            float* sxr = sx + (size_t)(ce * 8) * XPAD + c;
            sxr[0 * XPAD] = fc - n0;
            sxr[1 * XPAD] = fc - n1;
            sxr[2 * XPAD] = fc - n2;
            sxr[3 * XPAD] = fc - n3;
            sxr[4 * XPAD] = fc - n4;
            sxr[5 * XPAD] = fc - n5;
            sxr[6 * XPAD] = fc - n6;
            sxr[7 * XPAD] = fc - n7;
        }
    }
    __syncthreads();

    ull x2[32];
#pragma unroll
    for (int i = 0; i < 16; i++) {
        float4 v = *reinterpret_cast<float4*>(&sx[tid * XPAD + i * 4]);
        x2[2 * i + 0] = pack2(v.x, v.y);
        x2[2 * i + 1] = pack2(v.z, v.w);
    }

    ull o2[8];
#pragma unroll
    for (int i = 0; i < 8; i++) o2[i] = pack2(sb1[2 * i], sb1[2 * i + 1]);

#pragma unroll 4
    for (int t = 0; t < 64; t++) {
        const ull* w2 = reinterpret_cast<const ull*>(&sW0[t * 64]);
        ull a0 = 0, a1 = 0, a2 = 0, a3 = 0;
#pragma unroll
        for (int i = 0; i < 8; i++) {
            FMA2(a0, x2[i +  0], w2[i +  0]);
            FMA2(a1, x2[i +  8], w2[i +  8]);
            FMA2(a2, x2[i + 16], w2[i + 16]);
            FMA2(a3, x2[i + 24], w2[i + 24]);
        }
        ADD2(a0, a1); ADD2(a2, a3); ADD2(a0, a2);
        float lo, hi; unpack2(a0, lo, hi);
        float h = fmaxf(lo + hi + sb0[t], 0.0f);
        ull h2 = pack2(h, h);
        const ull* w1 = reinterpret_cast<const ull*>(&sW1[t * 16]);
#pragma unroll
        for (int i = 0; i < 8; i++) FMA2(o2[i], h2, w1[i]);
    }

    float o[16];
#pragma unroll
    for (int i = 0; i < 8; i++) unpack2(o2[i], o[2 * i], o[2 * i + 1]);

    float sq = 0.f;
#pragma unroll
    for (int i = 0; i < 16; i++) sq = fmaf(o[i], o[i], sq);
    float inv = 1.0f / (sqrtf(sq) + 1e-7f);
#pragma unroll
    for (int i = 0; i < 16; i++) o[i] *= inv;

    size_t row = (size_t)b * Sn + chunk * 256 + tid;
    float* dst = (mb < Bn ? g_fq : g_fk) + row * OUTC;
#pragma unroll
    for (int oo = 0; oo < 4; oo++)
        *reinterpret_cast<float4*>(&dst[oo * 4]) =
            make_float4(o[oo * 4 + 0], o[oo * 4 + 1], o[oo * 4 + 2], o[oo * 4 + 3]);

    uint32_t hb[8];
#pragma unroll
    for (int i = 0; i < 8; i++) PACKBF(hb[i], o[2 * i], o[2 * i + 1]);
    uint32_t* dsth = reinterpret_cast<uint32_t*>(
        (mb < Bn ? g_fqh : g_fkh) + row * OUTC);
#pragma unroll
    for (int i = 0; i < 2; i++)
        reinterpret_cast<uint4*>(dsth)[i] =
            make_uint4(hb[4 * i + 0], hb[4 * i + 1], hb[4 * i + 2], hb[4 * i + 3]);
}

// ---------------------------------------------------------------------------
// Kernel C v2: HMMA Gram, grid doubled via (64 rows) x (2 t-halves) split.
//   grid = 8b x 32rb = 256 blocks, 256 threads.
//   Warp w: row sub-block wr = w&3 (16 rows), t-half th = w>>2 (1024 k rows).
//   Halves combine through smem; th=0 warps do diagonal + loss.
// ---------------------------------------------------------------------------
__global__ __launch_bounds__(256) void gram_kernel(float* __restrict__ out) {
    extern __shared__ uint32_t sk[];      // B0[2048*4] | B1[2048*4]  (64 KB)
    __shared__ float s_part[4][8][2];
    __shared__ float s_wred[4];

    int tid  = threadIdx.x;
    int w    = tid >> 5;
    int lane = tid & 31;
    int g    = lane >> 2;                 // groupID 0..7
    int t    = lane & 3;                  // threadID-in-group
    int b    = blockIdx.x >> 5;
    int rb   = blockIdx.x & 31;
    int wr   = w & 3;                     // row sub-block
    int th   = w >> 2;                    // t-half

    uint32_t* B0 = sk;
    uint32_t* B1 = sk + Sn * 4;

    const uint32_t* ksrc = reinterpret_cast<const uint32_t*>(g_fkh) +
                           (size_t)b * Sn * 8;
    for (int idx = tid; idx < Sn * 8; idx += 256) {
        int n = idx >> 3, j = idx & 7;
        uint32_t v = __ldg(&ksrc[idx]);
        if (j < 4) B0[n * 4 + j] = v;
        else       B1[n * 4 + (j - 4)] = v;
    }

    int r0 = rb * 64 + wr * 16 + g;
    const uint32_t* qu = reinterpret_cast<const uint32_t*>(g_fqh) +
                         (size_t)b * Sn * 8;
    uint32_t a0 = __ldg(&qu[(size_t)r0 * 8 + t]);
    uint32_t a1 = __ldg(&qu[(size_t)(r0 + 8) * 8 + t]);
    uint32_t a2 = __ldg(&qu[(size_t)r0 * 8 + t + 4]);
    uint32_t a3 = __ldg(&qu[(size_t)(r0 + 8) * 8 + t + 4]);

    __syncthreads();

    float s0 = 0.f, s1 = 0.f;

    // this warp's t-half: n-tiles [th*128, th*128+128)
    for (int j = th * 128; j < th * 128 + 128; j += 2) {
        int nA = (j + 0) * 8 + g;
        int nB = (j + 1) * 8 + g;
        uint32_t bA0 = B0[nA * 4 + t], bA1 = B1[nA * 4 + t];
        uint32_t bB0 = B0[nB * 4 + t], bB1 = B1[nB * 4 + t];

        float dA0, dA1, dA2, dA3, dB0, dB1, dB2, dB3;
        mma16816(dA0, dA1, dA2, dA3, a0, a1, a2, a3, bA0, bA1);
        mma16816(dB0, dB1, dB2, dB3, a0, a1, a2, a3, bB0, bB1);

        s0 += ex2f(fmaf(dA0, F_SCALE, -F_SCALE));
        s0 += ex2f(fmaf(dA1, F_SCALE, -F_SCALE));
        s1 += ex2f(fmaf(dA2, F_SCALE, -F_SCALE));
        s1 += ex2f(fmaf(dA3, F_SCALE, -F_SCALE));
        s0 += ex2f(fmaf(dB0, F_SCALE, -F_SCALE));
        s0 += ex2f(fmaf(dB1, F_SCALE, -F_SCALE));
        s1 += ex2f(fmaf(dB2, F_SCALE, -F_SCALE));
        s1 += ex2f(fmaf(dB3, F_SCALE, -F_SCALE));
    }

    // lane-reduce across the 4 column lanes of each row group
    s0 += __shfl_xor_sync(0xFFFFFFFFu, s0, 1);
    s0 += __shfl_xor_sync(0xFFFFFFFFu, s0, 2);
    s1 += __shfl_xor_sync(0xFFFFFFFFu, s1, 1);
    s1 += __shfl_xor_sync(0xFFFFFFFFu, s1, 2);

    // combine the two t-halves via smem
    if (th == 1 && t == 0) {
        s_part[wr][g][0] = s0;
        s_part[wr][g][1] = s1;
    }
    __syncthreads();

    float loss = 0.f;
    if (th == 0 && t == 0) {
        s0 += s_part[wr][g][0];
        s1 += s_part[wr][g][1];
#pragma unroll
        for (int rr = 0; rr < 2; rr++) {
            int r = (rr == 0) ? r0 : r0 + 8;
            float sum = (rr == 0) ? s0 : s1;
            size_t grow = (size_t)b * Sn + r;
            const float4* qr = reinterpret_cast<const float4*>(g_fq + grow * OUTC);
            const float4* kr = reinterpret_cast<const float4*>(g_fk + grow * OUTC);
            float d = 0.f;
#pragma unroll
            for (int jj = 0; jj < 4; jj++) {
                float4 qv = __ldg(&qr[jj]);
                float4 kv = __ldg(&kr[jj]);
                d = fmaf(qv.x, kv.x, d); d = fmaf(qv.y, kv.y, d);
                d = fmaf(qv.z, kv.z, d); d = fmaf(qv.w, kv.w, d);
            }
            loss += F_LN2 * (lg2f(sum) - F_SCALE * (d - 1.0f));
        }
    }

#pragma unroll
    for (int o = 16; o > 0; o >>= 1)
        loss += __shfl_xor_sync(0xFFFFFFFFu, loss, o);
    if (th == 0 && lane == 0) s_wred[wr] = loss;
    __syncthreads();
    if (tid == 0) {
        float acc = (s_wred[0] + s_wred[1]) + (s_wred[2] + s_wred[3]);
        atomicAdd(out, acc * (1.0f / (float)(Bn * Sn)));
    }
}

// ---------------------------------------------------------------------------
extern "C" void kernel_launch(void* const* d_in, const int* in_sizes, int n_in,
                              void* d_out, int out_size) {
    const float* f_q  = (const float*)d_in[0];
    const float* f_k  = (const float*)d_in[1];
    const float* W0   = (const float*)d_in[2];
    const float* b0   = (const float*)d_in[3];
    const float* W1   = (const float*)d_in[4];
    const float* b1   = (const float*)d_in[5];
    const int*   c_id = (const int*)d_in[6];
    float* out = (float*)d_out;

    int gmlp_smem = (256 * XPAD + 64 * 64 + 64 * 16 + 64 + 16) * (int)sizeof(float);
    cudaFuncSetAttribute(gmlp_kernel,
                         cudaFuncAttributeMaxDynamicSharedMemorySize, gmlp_smem);
    int gram_smem = Sn * 8 * (int)sizeof(uint32_t);   // 64 KB
    cudaFuncSetAttribute(gram_kernel,
                         cudaFuncAttributeMaxDynamicSharedMemorySize, gram_smem);

    gmlp_kernel<<<16 * 8, 256, gmlp_smem>>>(f_q, f_k, c_id, W0, b0, W1, b1, out);
    gram_kernel<<<Bn * 32, 256, gram_smem>>>(out);
}

// round 16
// speedup vs baseline: 1.1968x; 1.0230x over previous
#include <cuda_runtime.h>
#include <cuda_bf16.h>
#include <math.h>
#include <cstdint>

#define Bn 8
#define Cn 64
#define HW 65536
#define Sn 2048
#define OUTC 16

#define F_SCALE     20.6096954f                   /* log2(e)/0.07 */
#define F_LN2       0.69314718056f

typedef unsigned long long ull;
__device__ __forceinline__ ull pack2(float lo, float hi) {
    ull r;
    asm("mov.b64 %0, {%1, %2};" : "=l"(r) : "r"(__float_as_uint(lo)), "r"(__float_as_uint(hi)));
    return r;
}
__device__ __forceinline__ void unpack2(ull v, float& lo, float& hi) {
    unsigned a, b;
    asm("mov.b64 {%0, %1}, %2;" : "=r"(a), "=r"(b) : "l"(v));
    lo = __uint_as_float(a); hi = __uint_as_float(b);
}
#define FMA2(d, a, b) asm("fma.rn.f32x2 %0, %1, %2, %3;" : "=l"(d) : "l"(a), "l"(b), "l"(d))
#define ADD2(d, a)    asm("add.rn.f32x2 %0, %1, %2;"     : "=l"(d) : "l"(a), "l"(d))
__device__ __forceinline__ float ex2f(float x) {
    float y; asm("ex2.approx.f32 %0, %1;" : "=f"(y) : "f"(x)); return y;
}
__device__ __forceinline__ float lg2f(float x) {
    float y; asm("lg2.approx.f32 %0, %1;" : "=f"(y) : "f"(x)); return y;
}
#define PACKBF(d, lo, hi) \
    asm("cvt.rn.bf16x2.f32 %0, %1, %2;" : "=r"(d) : "f"(hi), "f"(lo))

// m16n8k16 bf16 MMA, C = 0
__device__ __forceinline__ void mma16816(float& d0, float& d1, float& d2, float& d3,
                                         uint32_t a0, uint32_t a1, uint32_t a2, uint32_t a3,
                                         uint32_t b0, uint32_t b1) {
    asm("mma.sync.aligned.m16n8k16.row.col.f32.bf16.bf16.f32 "
        "{%0,%1,%2,%3}, {%4,%5,%6,%7}, {%8,%9}, {%10,%11,%12,%13};"
        : "=f"(d0), "=f"(d1), "=f"(d2), "=f"(d3)
        : "r"(a0), "r"(a1), "r"(a2), "r"(a3), "r"(b0), "r"(b1),
          "f"(0.0f), "f"(0.0f), "f"(0.0f), "f"(0.0f));
}

// Scratch
__device__ float g_fq[Bn * Sn * OUTC];
__device__ float g_fk[Bn * Sn * OUTC];
__device__ __align__(16) __nv_bfloat16 g_fqh[Bn * Sn * OUTC];
__device__ __align__(16) __nv_bfloat16 g_fkh[Bn * Sn * OUTC];

// ---------------------------------------------------------------------------
// Kernel AB (fused): gather stencil diffs into smem, MLP + L2-norm.
// (unchanged from R14 win)
// ---------------------------------------------------------------------------
#define XPAD 68
__global__ __launch_bounds__(256) void gmlp_kernel(const float* __restrict__ fq,
                                                   const float* __restrict__ fk,
                                                   const int*   __restrict__ c_ids,
                                                   const float* __restrict__ W0,
                                                   const float* __restrict__ b0,
                                                   const float* __restrict__ W1,
                                                   const float* __restrict__ b1,
                                                   float* __restrict__ out) {
    extern __shared__ float smem[];
    float* sx  = smem;                       // 256*68
    float* sW0 = sx + 256 * XPAD;            // 64*64 (transposed)
    float* sW1 = sW0 + 64 * 64;              // 64*16
    float* sb0 = sW1 + 64 * 16;              // 64
    float* sb1 = sb0 + 64;                   // 16

    if (blockIdx.x == 0 && threadIdx.x == 0) out[0] = 0.0f;

    int mb    = blockIdx.x >> 3;
    int chunk = blockIdx.x & 7;
    int tid   = threadIdx.x;
    int b     = (mb < Bn) ? mb : mb - Bn;

    for (int i = tid; i < 4096; i += 256) {
        int c = i >> 6, t = i & 63;
        sW0[t * 64 + c] = __ldg(&W0[i]);
    }
    for (int i = tid; i < 1024; i += 256) sW1[i] = __ldg(&W1[i]);
    if (tid < 64) sb0[tid] = __ldg(&b0[tid]);
    if (tid < 16) sb1[tid] = __ldg(&b1[tid]);

    {
        int c   = tid & 63;
        int ce0 = tid >> 6;
        const float* featc = ((mb < Bn) ? fq : fk) + ((size_t)b * Cn + c) * HW;
#pragma unroll
        for (int k = 0; k < 8; k++) {
            int ce = ce0 + 4 * k;
            int ic = __ldg(&c_ids[chunk * 32 + ce]);
            const float* p = featc + ic;
            float fc  = __ldg(p);
            float n0  = __ldg(p - 257);
            float n1  = __ldg(p - 256);
            float n2  = __ldg(p - 255);
            float n3  = __ldg(p - 1);
            float n4  = __ldg(p + 1);
            float n5  = __ldg(p + 255);
            float n6  = __ldg(p + 256);
            float n7  = __ldg(p + 257);
            float* sxr = sx + (size_t)(ce * 8) * XPAD + c;
            sxr[0 * XPAD] = fc - n0;
            sxr[1 * XPAD] = fc - n1;
            sxr[2 * XPAD] = fc - n2;
            sxr[3 * XPAD] = fc - n3;
            sxr[4 * XPAD] = fc - n4;
            sxr[5 * XPAD] = fc - n5;
            sxr[6 * XPAD] = fc - n6;
            sxr[7 * XPAD] = fc - n7;
        }
    }
    __syncthreads();

    ull x2[32];
#pragma unroll
    for (int i = 0; i < 16; i++) {
        float4 v = *reinterpret_cast<float4*>(&sx[tid * XPAD + i * 4]);
        x2[2 * i + 0] = pack2(v.x, v.y);
        x2[2 * i + 1] = pack2(v.z, v.w);
    }

    ull o2[8];
#pragma unroll
    for (int i = 0; i < 8; i++) o2[i] = pack2(sb1[2 * i], sb1[2 * i + 1]);

#pragma unroll 4
    for (int t = 0; t < 64; t++) {
        const ull* w2 = reinterpret_cast<const ull*>(&sW0[t * 64]);
        ull a0 = 0, a1 = 0, a2 = 0, a3 = 0;
#pragma unroll
        for (int i = 0; i < 8; i++) {
            FMA2(a0, x2[i +  0], w2[i +  0]);
            FMA2(a1, x2[i +  8], w2[i +  8]);
            FMA2(a2, x2[i + 16], w2[i + 16]);
            FMA2(a3, x2[i + 24], w2[i + 24]);
        }
        ADD2(a0, a1); ADD2(a2, a3); ADD2(a0, a2);
        float lo, hi; unpack2(a0, lo, hi);
        float h = fmaxf(lo + hi + sb0[t], 0.0f);
        ull h2 = pack2(h, h);
        const ull* w1 = reinterpret_cast<const ull*>(&sW1[t * 16]);
#pragma unroll
        for (int i = 0; i < 8; i++) FMA2(o2[i], h2, w1[i]);
    }

    float o[16];
#pragma unroll
    for (int i = 0; i < 8; i++) unpack2(o2[i], o[2 * i], o[2 * i + 1]);

    float sq = 0.f;
#pragma unroll
    for (int i = 0; i < 16; i++) sq = fmaf(o[i], o[i], sq);
    float inv = 1.0f / (sqrtf(sq) + 1e-7f);
#pragma unroll
    for (int i = 0; i < 16; i++) o[i] *= inv;

    size_t row = (size_t)b * Sn + chunk * 256 + tid;
    float* dst = (mb < Bn ? g_fq : g_fk) + row * OUTC;
#pragma unroll
    for (int oo = 0; oo < 4; oo++)
        *reinterpret_cast<float4*>(&dst[oo * 4]) =
            make_float4(o[oo * 4 + 0], o[oo * 4 + 1], o[oo * 4 + 2], o[oo * 4 + 3]);

    uint32_t hb[8];
#pragma unroll
    for (int i = 0; i < 8; i++) PACKBF(hb[i], o[2 * i], o[2 * i + 1]);
    uint32_t* dsth = reinterpret_cast<uint32_t*>(
        (mb < Bn ? g_fqh : g_fkh) + row * OUTC);
#pragma unroll
    for (int i = 0; i < 2; i++)
        reinterpret_cast<uint4*>(dsth)[i] =
            make_uint4(hb[4 * i + 0], hb[4 * i + 1], hb[4 * i + 2], hb[4 * i + 3]);
}

// ---------------------------------------------------------------------------
// Kernel C v3: HMMA Gram, 512 threads = 16 warps.
//   grid = 8b x 32rb = 256 blocks (64 rows each); warp w: row sub-block
//   wr = w&3 (16 rows), t-quarter th = w>>2 (512 k rows, 32 iters).
//   2 blocks/SM co-resident -> ~7 warps/SMSP to hide LDS/MMA/MUFU chains.
//   Quarters combine via smem; th=0 warps do diagonal + loss.
// ---------------------------------------------------------------------------
__global__ __launch_bounds__(512) void gram_kernel(float* __restrict__ out) {
    extern __shared__ uint32_t sk[];      // B0[2048*4] | B1[2048*4]  (64 KB)
    __shared__ float s_part[4][4][8][2];  // [th][wr][g][rr]
    __shared__ float s_wred[4];

    int tid  = threadIdx.x;
    int w    = tid >> 5;                  // 0..15
    int lane = tid & 31;
    int g    = lane >> 2;                 // groupID 0..7
    int t    = lane & 3;                  // threadID-in-group
    int b    = blockIdx.x >> 5;
    int rb   = blockIdx.x & 31;
    int wr   = w & 3;                     // row sub-block
    int th   = w >> 2;                    // t-quarter 0..3

    uint32_t* B0 = sk;
    uint32_t* B1 = sk + Sn * 4;

    const uint32_t* ksrc = reinterpret_cast<const uint32_t*>(g_fkh) +
                           (size_t)b * Sn * 8;
    for (int idx = tid; idx < Sn * 8; idx += 512) {
        int n = idx >> 3, j = idx & 7;
        uint32_t v = __ldg(&ksrc[idx]);
        if (j < 4) B0[n * 4 + j] = v;
        else       B1[n * 4 + (j - 4)] = v;
    }

    int r0 = rb * 64 + wr * 16 + g;
    const uint32_t* qu = reinterpret_cast<const uint32_t*>(g_fqh) +
                         (size_t)b * Sn * 8;
    uint32_t a0 = __ldg(&qu[(size_t)r0 * 8 + t]);
    uint32_t a1 = __ldg(&qu[(size_t)(r0 + 8) * 8 + t]);
    uint32_t a2 = __ldg(&qu[(size_t)r0 * 8 + t + 4]);
    uint32_t a3 = __ldg(&qu[(size_t)(r0 + 8) * 8 + t + 4]);

    __syncthreads();

    float s0 = 0.f, s1 = 0.f;

    // this warp's t-quarter: n-tiles [th*64, th*64+64)
    for (int j = th * 64; j < th * 64 + 64; j += 2) {
        int nA = (j + 0) * 8 + g;
        int nB = (j + 1) * 8 + g;
        uint32_t bA0 = B0[nA * 4 + t], bA1 = B1[nA * 4 + t];
        uint32_t bB0 = B0[nB * 4 + t], bB1 = B1[nB * 4 + t];

        float dA0, dA1, dA2, dA3, dB0, dB1, dB2, dB3;
        mma16816(dA0, dA1, dA2, dA3, a0, a1, a2, a3, bA0, bA1);
        mma16816(dB0, dB1, dB2, dB3, a0, a1, a2, a3, bB0, bB1);

        s0 += ex2f(fmaf(dA0, F_SCALE, -F_SCALE));
        s0 += ex2f(fmaf(dA1, F_SCALE, -F_SCALE));
        s1 += ex2f(fmaf(dA2, F_SCALE, -F_SCALE));
        s1 += ex2f(fmaf(dA3, F_SCALE, -F_SCALE));
        s0 += ex2f(fmaf(dB0, F_SCALE, -F_SCALE));
        s0 += ex2f(fmaf(dB1, F_SCALE, -F_SCALE));
        s1 += ex2f(fmaf(dB2, F_SCALE, -F_SCALE));
        s1 += ex2f(fmaf(dB3, F_SCALE, -F_SCALE));
    }

    // lane-reduce across the 4 column lanes of each row group
    s0 += __shfl_xor_sync(0xFFFFFFFFu, s0, 1);
    s0 += __shfl_xor_sync(0xFFFFFFFFu, s0, 2);
    s1 += __shfl_xor_sync(0xFFFFFFFFu, s1, 1);
    s1 += __shfl_xor_sync(0xFFFFFFFFu, s1, 2);

    // combine the four t-quarters via smem
    if (th != 0 && t == 0) {
        s_part[th][wr][g][0] = s0;
        s_part[th][wr][g][1] = s1;
    }
    __syncthreads();

    float loss = 0.f;
    if (th == 0 && t == 0) {
#pragma unroll
        for (int q = 1; q < 4; q++) {
            s0 += s_part[q][wr][g][0];
            s1 += s_part[q][wr][g][1];
        }
#pragma unroll
        for (int rr = 0; rr < 2; rr++) {
            int r = (rr == 0) ? r0 : r0 + 8;
            float sum = (rr == 0) ? s0 : s1;
            size_t grow = (size_t)b * Sn + r;
            const float4* qr = reinterpret_cast<const float4*>(g_fq + grow * OUTC);
            const float4* kr = reinterpret_cast<const float4*>(g_fk + grow * OUTC);
            float d = 0.f;
#pragma unroll
            for (int jj = 0; jj < 4; jj++) {
                float4 qv = __ldg(&qr[jj]);
                float4 kv = __ldg(&kr[jj]);
                d = fmaf(qv.x, kv.x, d); d = fmaf(qv.y, kv.y, d);
                d = fmaf(qv.z, kv.z, d); d = fmaf(qv.w, kv.w, d);
            }
            loss += F_LN2 * (lg2f(sum) - F_SCALE * (d - 1.0f));
        }
    }

#pragma unroll
    for (int o = 16; o > 0; o >>= 1)
        loss += __shfl_xor_sync(0xFFFFFFFFu, loss, o);
    if (th == 0 && lane == 0) s_wred[wr] = loss;
    __syncthreads();
    if (tid == 0) {
        float acc = (s_wred[0] + s_wred[1]) + (s_wred[2] + s_wred[3]);
        atomicAdd(out, acc * (1.0f / (float)(Bn * Sn)));
    }
}

// ---------------------------------------------------------------------------
extern "C" void kernel_launch(void* const* d_in, const int* in_sizes, int n_in,
                              void* d_out, int out_size) {
    const float* f_q  = (const float*)d_in[0];
    const float* f_k  = (const float*)d_in[1];
    const float* W0   = (const float*)d_in[2];
    const float* b0   = (const float*)d_in[3];
    const float* W1   = (const float*)d_in[4];
    const float* b1   = (const float*)d_in[5];
    const int*   c_id = (const int*)d_in[6];
    float* out = (float*)d_out;

    int gmlp_smem = (256 * XPAD + 64 * 64 + 64 * 16 + 64 + 16) * (int)sizeof(float);
    cudaFuncSetAttribute(gmlp_kernel,
                         cudaFuncAttributeMaxDynamicSharedMemorySize, gmlp_smem);
    int gram_smem = Sn * 8 * (int)sizeof(uint32_t);   // 64 KB
    cudaFuncSetAttribute(gram_kernel,
                         cudaFuncAttributeMaxDynamicSharedMemorySize, gram_smem);

    gmlp_kernel<<<16 * 8, 256, gmlp_smem>>>(f_q, f_k, c_id, W0, b0, W1, b1, out);
    gram_kernel<<<Bn * 32, 512, gram_smem>>>(out);
}